// round 3
// baseline (speedup 1.0000x reference)
#include <cuda_runtime.h>
#include <cuda_bf16.h>

#define NN   2048
#define EE   65536
#define FIN  128
#define HH   16
#define N2   (NN * NN)
#define G1   256
#define TPB  256

// ---------------- scratch (no allocations allowed) ----------------
// All mutable state is reset in k5_pair's tail so every graph replay starts
// clean. Load-time zero-init covers the first call.
__device__ __align__(16) float g_deg[NN];
__device__ __align__(16) float g_xw1[NN * HH];
__device__ __align__(16) float g_acc1[NN * HH];
__device__ __align__(16) float g_hw2[NN * 2];
__device__ __align__(16) float g_acc2[NN * 2];
__device__ __align__(16) float g_A[NN * HH];   // h @ Wc1[0:16] + bc1
__device__ __align__(16) float g_B[NN * HH];   // h @ Wc1[16:32]
__device__ unsigned g_bar;                     // grid barrier counter

// ---------------- per-thread edge_index layout detection ----------------
// int64 data: first 8 u64 words all < 2048 -> OR < 2048.
// int32 data: each u64 packs two ids; OR high half nonzero w.p. 1-(1/2048)^8.
__device__ __forceinline__ bool detect_is32(const void* ei) {
    const unsigned long long* p = (const unsigned long long*)ei;
    unsigned long long v = p[0] | p[1] | p[2] | p[3] | p[4] | p[5] | p[6] | p[7];
    return v >= 2048ULL;
}

__device__ __forceinline__ void ld_edge(const void* ei, int e, bool is32,
                                        int& s, int& d) {
    if (is32) {
        s = ((const int*)ei)[e];
        d = ((const int*)ei)[EE + e];
    } else {
        s = (int)(((const long long*)ei)[e]);
        d = (int)(((const long long*)ei)[EE + e]);
    }
}

__device__ __forceinline__ void red_add_v4(float* p, float a, float b, float c, float d) {
    asm volatile("red.global.add.v4.f32 [%0], {%1,%2,%3,%4};"
                 :: "l"(p), "f"(a), "f"(b), "f"(c), "f"(d) : "memory");
}
__device__ __forceinline__ void red_add_v2(float* p, float a, float b) {
    asm volatile("red.global.add.v2.f32 [%0], {%1,%2};"
                 :: "l"(p), "f"(a), "f"(b) : "memory");
}

// Grid barrier: all 256 blocks are co-resident (256 blocks x 256 thr on 148
// SMs, <=256 regs/thread -> >=2 blocks/SM guaranteed), so spinning is safe.
__device__ __forceinline__ void gbar(unsigned target) {
    __syncthreads();
    if (threadIdx.x == 0) {
        asm volatile("red.release.gpu.global.add.u32 [%0], %1;"
                     :: "l"(&g_bar), "r"(1u) : "memory");
        unsigned v;
        do {
            asm volatile("ld.acquire.gpu.global.u32 %0, [%1];"
                         : "=r"(v) : "l"(&g_bar) : "memory");
            if (v < target) __nanosleep(32);
        } while (v < target);
    }
    __syncthreads();
}

// ================= k_front: everything before the pair MLP ================
__global__ void __launch_bounds__(TPB) k_front(
        const float* __restrict__ x,  const float* __restrict__ W1,
        const void*  __restrict__ ei, const float* __restrict__ b1,
        const float* __restrict__ W2, const float* __restrict__ Wc1,
        const float* __restrict__ bc1, float* __restrict__ out) {
    int id = blockIdx.x * TPB + threadIdx.x;     // 0..65535, == edge id
    bool is32 = detect_is32(ei);

    // ---- Phase A: degree + xw1 = x@W1 + index-block writes ----
    if (id < NN) atomicAdd(&g_deg[id], 1.f);     // self loop
    {
        int s, d;
        ld_edge(ei, id, is32, s, d);
        (void)s;
        atomicAdd(&g_deg[d], 1.f);
    }
    if (id < NN * HH) {
        int i = id >> 4, f = id & 15;
        const float4* xr = (const float4*)(x + i * FIN);
        float sum = 0.f;
        #pragma unroll
        for (int k4i = 0; k4i < FIN / 4; k4i++) {
            float4 xv = xr[k4i];
            int k = k4i * 4;
            sum = fmaf(xv.x, W1[(k + 0) * HH + f], sum);
            sum = fmaf(xv.y, W1[(k + 1) * HH + f], sum);
            sum = fmaf(xv.z, W1[(k + 2) * HH + f], sum);
            sum = fmaf(xv.w, W1[(k + 3) * HH + f], sum);
        }
        g_xw1[id] = sum;
    }
    // full_edge_index writes (32MB, zero dependencies -> overlap barriers)
    {
        float4* s0 = (float4*)(out + NN * 2 + N2);
        float4* s1 = (float4*)(out + NN * 2 + 2 * N2);
        #pragma unroll
        for (int t = 0; t < 16; t++) {
            int q = id + t * (G1 * TPB);         // 0 .. N2/4-1
            float fi = (float)(q >> 9);          // 512 float4 per row
            s0[q] = make_float4(fi, fi, fi, fi);
            float fj = (float)((q & 511) * 4);
            s1[q] = make_float4(fj, fj + 1.f, fj + 2.f, fj + 3.f);
        }
    }
    gbar(G1);

    // ---- Phase B: scatter layer 1 ----
    {
        int s, d;
        ld_edge(ei, id, is32, s, d);
        float nrm = rsqrtf(g_deg[s]) * rsqrtf(g_deg[d]);
        const float4* xs = (const float4*)&g_xw1[s * HH];
        float4 v0 = xs[0], v1 = xs[1], v2 = xs[2], v3 = xs[3];
        float* ad = &g_acc1[d * HH];
        red_add_v4(ad + 0,  nrm * v0.x, nrm * v0.y, nrm * v0.z, nrm * v0.w);
        red_add_v4(ad + 4,  nrm * v1.x, nrm * v1.y, nrm * v1.z, nrm * v1.w);
        red_add_v4(ad + 8,  nrm * v2.x, nrm * v2.y, nrm * v2.z, nrm * v2.w);
        red_add_v4(ad + 12, nrm * v3.x, nrm * v3.y, nrm * v3.z, nrm * v3.w);
    }
    gbar(2 * G1);

    // ---- Phase C: h = relu(gcn1); hw2 = h@W2; A/B for pair MLP ----
    if (id < NN) {
        int i = id;
        float d2 = 1.f / g_deg[i];
        float h[HH];
        #pragma unroll
        for (int f = 0; f < HH; f++) {
            float v = g_acc1[i * HH + f] + d2 * g_xw1[i * HH + f] + b1[f];
            h[f] = fmaxf(v, 0.f);
        }
        float c0 = 0.f, c1 = 0.f;
        #pragma unroll
        for (int f = 0; f < HH; f++) {
            c0 = fmaf(h[f], W2[f * 2 + 0], c0);
            c1 = fmaf(h[f], W2[f * 2 + 1], c1);
        }
        g_hw2[i * 2 + 0] = c0;
        g_hw2[i * 2 + 1] = c1;
        #pragma unroll
        for (int o = 0; o < HH; o++) {
            float a = bc1[o], b = 0.f;
            #pragma unroll
            for (int f = 0; f < HH; f++) {
                a = fmaf(h[f], Wc1[f * HH + o], a);
                b = fmaf(h[f], Wc1[(HH + f) * HH + o], b);
            }
            g_A[i * HH + o] = a;
            g_B[i * HH + o] = b;
        }
    }
    gbar(3 * G1);

    // ---- Phase D: scatter layer 2 ----
    {
        int s, d;
        ld_edge(ei, id, is32, s, d);
        float nrm = rsqrtf(g_deg[s]) * rsqrtf(g_deg[d]);
        red_add_v2(&g_acc2[d * 2], nrm * g_hw2[s * 2 + 0], nrm * g_hw2[s * 2 + 1]);
    }
}

// One B-row load serves two i-rows. NO address-taking of register structs.
__device__ __forceinline__ void pair2(const float* A0, const float* A1,
                                      const float* w, float bb, int j,
                                      float& o0, float& o1) {
    const float4* bp = (const float4*)&g_B[j * HH];
    float4 q0 = bp[0], q1 = bp[1], q2 = bp[2], q3 = bp[3];
    float s0 = bb, s1 = bb;
#define PT(idx, comp) { float bv = comp; \
    s0 = fmaf(fmaxf(A0[idx] + bv, 0.f), w[idx], s0); \
    s1 = fmaf(fmaxf(A1[idx] + bv, 0.f), w[idx], s1); }
    PT(0,  q0.x) PT(1,  q0.y) PT(2,  q0.z) PT(3,  q0.w)
    PT(4,  q1.x) PT(5,  q1.y) PT(6,  q1.z) PT(7,  q1.w)
    PT(8,  q2.x) PT(9,  q2.y) PT(10, q2.z) PT(11, q2.w)
    PT(12, q3.x) PT(13, q3.y) PT(14, q3.z) PT(15, q3.w)
#undef PT
    o0 = 1.f / (1.f + __expf(-s0));
    o1 = 1.f / (1.f + __expf(-s1));
}

// ================= k5: pair MLP (2 rows / block) + node_out + reset =======
__global__ void __launch_bounds__(TPB) k5_pair(const float* __restrict__ Wc2,
                                               const float* __restrict__ bc2p,
                                               const float* __restrict__ b2,
                                               float* __restrict__ out) {
    int b = blockIdx.x;            // 0..1023
    int i0 = b * 2, i1 = i0 + 1;
    int t = threadIdx.x;

    float A0[HH], A1[HH], w[HH];
    {
        const float4* p0 = (const float4*)&g_A[i0 * HH];
        const float4* p1 = (const float4*)&g_A[i1 * HH];
        float4 r;
        r = p0[0]; A0[0]=r.x; A0[1]=r.y; A0[2]=r.z; A0[3]=r.w;
        r = p0[1]; A0[4]=r.x; A0[5]=r.y; A0[6]=r.z; A0[7]=r.w;
        r = p0[2]; A0[8]=r.x; A0[9]=r.y; A0[10]=r.z; A0[11]=r.w;
        r = p0[3]; A0[12]=r.x; A0[13]=r.y; A0[14]=r.z; A0[15]=r.w;
        r = p1[0]; A1[0]=r.x; A1[1]=r.y; A1[2]=r.z; A1[3]=r.w;
        r = p1[1]; A1[4]=r.x; A1[5]=r.y; A1[6]=r.z; A1[7]=r.w;
        r = p1[2]; A1[8]=r.x; A1[9]=r.y; A1[10]=r.z; A1[11]=r.w;
        r = p1[3]; A1[12]=r.x; A1[13]=r.y; A1[14]=r.z; A1[15]=r.w;
    }
    #pragma unroll
    for (int f = 0; f < HH; f++) w[f] = Wc2[f];
    float bb = bc2p[0];

    float4* eo0 = (float4*)(out + NN * 2 + i0 * NN);
    float4* eo1 = (float4*)(out + NN * 2 + i1 * NN);

    #pragma unroll
    for (int it = 0; it < NN / (TPB * 4); it++) {       // 2 iters
        int v = it * TPB + t;
        int jb = v * 4;
        float r0, r1, r2, r3, u0, u1, u2, u3;
        pair2(A0, A1, w, bb, jb + 0, r0, u0);
        pair2(A0, A1, w, bb, jb + 1, r1, u1);
        pair2(A0, A1, w, bb, jb + 2, r2, u2);
        pair2(A0, A1, w, bb, jb + 3, r3, u3);
        eo0[v] = make_float4(r0, r1, r2, r3);
        eo1[v] = make_float4(u0, u1, u2, u3);
    }

    // node_out for i0, i1 (must read acc2 BEFORE reset)
    if (t == 0 || t == 1) {
        int i = (t == 0) ? i0 : i1;
        float d2 = 1.f / g_deg[i];
        out[i * 2 + 0] = g_acc2[i * 2 + 0] + d2 * g_hw2[i * 2 + 0] + b2[0];
        out[i * 2 + 1] = g_acc2[i * 2 + 1] + d2 * g_hw2[i * 2 + 1] + b2[1];
    }
    __syncthreads();
    // reset state for next replay
    if (t < 32)              g_acc1[i0 * HH + t] = 0.f;   // covers rows i0,i1
    else if (t < 36)         g_acc2[i0 * 2 + (t - 32)] = 0.f;
    else if (t == 36)        g_deg[i0] = 0.f;
    else if (t == 37)        g_deg[i1] = 0.f;
    else if (t == 38 && b == 0) g_bar = 0u;               // barrier counter
}

// ---------------- launch ----------------
extern "C" void kernel_launch(void* const* d_in, const int* in_sizes, int n_in,
                              void* d_out, int out_size) {
    const float* x   = (const float*)d_in[0];
    const void*  ei  = d_in[1];
    const float* W1  = (const float*)d_in[2];
    const float* b1  = (const float*)d_in[3];
    const float* W2  = (const float*)d_in[4];
    const float* b2  = (const float*)d_in[5];
    const float* Wc1 = (const float*)d_in[6];
    const float* bc1 = (const float*)d_in[7];
    const float* Wc2 = (const float*)d_in[8];
    const float* bc2 = (const float*)d_in[9];
    float* out = (float*)d_out;

    k_front<<<G1, TPB>>>(x, W1, ei, b1, W2, Wc1, bc1, out);
    k5_pair<<<NN / 2, TPB>>>(Wc2, bc2, b2, out);
}

// round 10
// speedup vs baseline: 2.4281x; 2.4281x over previous
#include <cuda_runtime.h>
#include <cuda_bf16.h>

#define NN   2048
#define EE   65536
#define FIN  128
#define HH   16
#define N2   (NN * NN)
#define G1   256
#define TPB  256

// ---------------- scratch (no allocations allowed) ----------------
// Mutable state is reset in k5_pair's tail so every graph replay starts clean.
__device__ __align__(16) float g_deg[NN];
__device__ __align__(16) float g_xw1[NN * HH];
__device__ __align__(16) float g_acc1[NN * HH];
__device__ __align__(16) float g_hw2[NN * 2];
__device__ __align__(16) float g_acc2[NN * 2];
__device__ __align__(16) float g_A[NN * HH];   // h @ Wc1[0:16] + bc1
__device__ __align__(16) float g_B[NN * HH];   // h @ Wc1[16:32]
__device__ unsigned g_bar;                     // grid barrier counter

// ---------------- per-thread edge_index layout detection ----------------
__device__ __forceinline__ bool detect_is32(const void* ei) {
    const unsigned long long* p = (const unsigned long long*)ei;
    unsigned long long v = p[0] | p[1] | p[2] | p[3] | p[4] | p[5] | p[6] | p[7];
    return v >= 2048ULL;
}

__device__ __forceinline__ void ld_edge(const void* ei, int e, bool is32,
                                        int& s, int& d) {
    if (is32) {
        s = ((const int*)ei)[e];
        d = ((const int*)ei)[EE + e];
    } else {
        s = (int)(((const long long*)ei)[e]);
        d = (int)(((const long long*)ei)[EE + e]);
    }
}

__device__ __forceinline__ void red_add_v4(float* p, float a, float b, float c, float d) {
    asm volatile("red.global.add.v4.f32 [%0], {%1,%2,%3,%4};"
                 :: "l"(p), "f"(a), "f"(b), "f"(c), "f"(d) : "memory");
}
__device__ __forceinline__ void red_add_v2(float* p, float a, float b) {
    asm volatile("red.global.add.v2.f32 [%0], {%1,%2};"
                 :: "l"(p), "f"(a), "f"(b) : "memory");
}

// sigmoid via single-MUFU tanh: sigmoid(s) = 0.5*tanh(0.5*s) + 0.5
__device__ __forceinline__ float sigmoid_tanh(float s) {
    float th;
    asm("tanh.approx.f32 %0, %1;" : "=f"(th) : "f"(0.5f * s));
    return fmaf(0.5f, th, 0.5f);
}

// Grid barrier: 256 blocks x 256 thr are guaranteed co-resident on 148 SMs.
__device__ __forceinline__ void gbar(unsigned target) {
    __syncthreads();
    if (threadIdx.x == 0) {
        asm volatile("red.release.gpu.global.add.u32 [%0], %1;"
                     :: "l"(&g_bar), "r"(1u) : "memory");
        unsigned v;
        do {
            asm volatile("ld.acquire.gpu.global.u32 %0, [%1];"
                         : "=r"(v) : "l"(&g_bar) : "memory");
            if (v < target) __nanosleep(32);
        } while (v < target);
    }
    __syncthreads();
}

// ================= k_front: GCN layers -> A,B,hw2,acc2 (small data only) ==
__global__ void __launch_bounds__(TPB) k_front(
        const float* __restrict__ x,  const float* __restrict__ W1,
        const void*  __restrict__ ei, const float* __restrict__ b1,
        const float* __restrict__ W2, const float* __restrict__ Wc1,
        const float* __restrict__ bc1) {
    int id = blockIdx.x * TPB + threadIdx.x;     // 0..65535 == edge id
    bool is32 = detect_is32(ei);

    // ---- Phase A: degree + xw1 = x@W1 ----
    if (id < NN) atomicAdd(&g_deg[id], 1.f);     // self loop
    {
        int s, d;
        ld_edge(ei, id, is32, s, d);
        (void)s;
        atomicAdd(&g_deg[d], 1.f);
    }
    if (id < NN * HH) {
        int i = id >> 4, f = id & 15;
        const float4* xr = (const float4*)(x + i * FIN);
        float sum = 0.f;
        #pragma unroll
        for (int k4i = 0; k4i < FIN / 4; k4i++) {
            float4 xv = xr[k4i];
            int k = k4i * 4;
            sum = fmaf(xv.x, W1[(k + 0) * HH + f], sum);
            sum = fmaf(xv.y, W1[(k + 1) * HH + f], sum);
            sum = fmaf(xv.z, W1[(k + 2) * HH + f], sum);
            sum = fmaf(xv.w, W1[(k + 3) * HH + f], sum);
        }
        g_xw1[id] = sum;
    }
    gbar(G1);

    // ---- Phase B: scatter layer 1 ----
    {
        int s, d;
        ld_edge(ei, id, is32, s, d);
        float nrm = rsqrtf(g_deg[s]) * rsqrtf(g_deg[d]);
        const float4* xs = (const float4*)&g_xw1[s * HH];
        float4 v0 = xs[0], v1 = xs[1], v2 = xs[2], v3 = xs[3];
        float* ad = &g_acc1[d * HH];
        red_add_v4(ad + 0,  nrm * v0.x, nrm * v0.y, nrm * v0.z, nrm * v0.w);
        red_add_v4(ad + 4,  nrm * v1.x, nrm * v1.y, nrm * v1.z, nrm * v1.w);
        red_add_v4(ad + 8,  nrm * v2.x, nrm * v2.y, nrm * v2.z, nrm * v2.w);
        red_add_v4(ad + 12, nrm * v3.x, nrm * v3.y, nrm * v3.z, nrm * v3.w);
    }
    gbar(2 * G1);

    // ---- Phase C: h = relu(gcn1); hw2 = h@W2; A/B for pair MLP ----
    if (id < NN) {
        int i = id;
        float d2 = 1.f / g_deg[i];
        float h[HH];
        #pragma unroll
        for (int f = 0; f < HH; f++) {
            float v = g_acc1[i * HH + f] + d2 * g_xw1[i * HH + f] + b1[f];
            h[f] = fmaxf(v, 0.f);
        }
        float c0 = 0.f, c1 = 0.f;
        #pragma unroll
        for (int f = 0; f < HH; f++) {
            c0 = fmaf(h[f], W2[f * 2 + 0], c0);
            c1 = fmaf(h[f], W2[f * 2 + 1], c1);
        }
        g_hw2[i * 2 + 0] = c0;
        g_hw2[i * 2 + 1] = c1;
        #pragma unroll
        for (int o = 0; o < HH; o++) {
            float a = bc1[o], b = 0.f;
            #pragma unroll
            for (int f = 0; f < HH; f++) {
                a = fmaf(h[f], Wc1[f * HH + o], a);
                b = fmaf(h[f], Wc1[(HH + f) * HH + o], b);
            }
            g_A[i * HH + o] = a;
            g_B[i * HH + o] = b;
        }
    }
    gbar(3 * G1);

    // ---- Phase D: scatter layer 2 ----
    {
        int s, d;
        ld_edge(ei, id, is32, s, d);
        float nrm = rsqrtf(g_deg[s]) * rsqrtf(g_deg[d]);
        red_add_v2(&g_acc2[d * 2], nrm * g_hw2[s * 2 + 0], nrm * g_hw2[s * 2 + 1]);
    }
}

// ================= k5: pair MLP + index writes + node_out + reset =========
// Block b owns rows i0..i0+3 (4 rows). Thread t handles j = q*256 + t:
// warp lanes load CONSECUTIVE B rows -> coalesced (16-line floor per LDG.128).
// Each B-row load feeds 4 output rows -> total B read traffic = 64MB.
__global__ void __launch_bounds__(TPB) k5_pair(const float* __restrict__ Wc2,
                                               const float* __restrict__ bc2p,
                                               const float* __restrict__ b2,
                                               float* __restrict__ out) {
    int b = blockIdx.x;            // 0..511
    int i0 = b * 4;
    int t = threadIdx.x;

    float A[4][HH], w[HH];
    #pragma unroll
    for (int r = 0; r < 4; r++) {
        const float4* ap = (const float4*)&g_A[(i0 + r) * HH];
        float4 v;
        v = ap[0]; A[r][0]=v.x;  A[r][1]=v.y;  A[r][2]=v.z;  A[r][3]=v.w;
        v = ap[1]; A[r][4]=v.x;  A[r][5]=v.y;  A[r][6]=v.z;  A[r][7]=v.w;
        v = ap[2]; A[r][8]=v.x;  A[r][9]=v.y;  A[r][10]=v.z; A[r][11]=v.w;
        v = ap[3]; A[r][12]=v.x; A[r][13]=v.y; A[r][14]=v.z; A[r][15]=v.w;
    }
    #pragma unroll
    for (int f = 0; f < HH; f++) w[f] = __ldg(&Wc2[f]);
    float bb = __ldg(&bc2p[0]);

    float* eo = out + NN * 2 + (long long)i0 * NN;

    #pragma unroll
    for (int q = 0; q < 8; q++) {
        int j = q * 256 + t;                       // warp-consecutive rows
        const float4* bp = (const float4*)&g_B[j * HH];
        float4 q0 = bp[0], q1 = bp[1], q2 = bp[2], q3 = bp[3];
        float s0 = bb, s1 = bb, s2 = bb, s3 = bb;
#define PT(idx, comp) { float bv = comp; \
        s0 = fmaf(fmaxf(A[0][idx] + bv, 0.f), w[idx], s0); \
        s1 = fmaf(fmaxf(A[1][idx] + bv, 0.f), w[idx], s1); \
        s2 = fmaf(fmaxf(A[2][idx] + bv, 0.f), w[idx], s2); \
        s3 = fmaf(fmaxf(A[3][idx] + bv, 0.f), w[idx], s3); }
        PT(0,  q0.x) PT(1,  q0.y) PT(2,  q0.z) PT(3,  q0.w)
        PT(4,  q1.x) PT(5,  q1.y) PT(6,  q1.z) PT(7,  q1.w)
        PT(8,  q2.x) PT(9,  q2.y) PT(10, q2.z) PT(11, q2.w)
        PT(12, q3.x) PT(13, q3.y) PT(14, q3.z) PT(15, q3.w)
#undef PT
        eo[j]          = sigmoid_tanh(s0);         // coalesced STG.32
        eo[NN + j]     = sigmoid_tanh(s1);
        eo[2 * NN + j] = sigmoid_tanh(s2);
        eo[3 * NN + j] = sigmoid_tanh(s3);
    }

    // full_edge_index rows for i0..i0+3 (independent of compute)
    {
        float4* s0p = (float4*)(out + NN * 2 + (long long)N2 + (long long)i0 * NN);
        float4* s1p = (float4*)(out + NN * 2 + 2LL * N2 + (long long)i0 * NN);
        #pragma unroll
        for (int it = 0; it < 2; it++) {
            int v = it * TPB + t;                  // 0..511 float4 per row
            float fj = (float)(v * 4);
            float4 ramp = make_float4(fj, fj + 1.f, fj + 2.f, fj + 3.f);
            #pragma unroll
            for (int r = 0; r < 4; r++) {
                float fi = (float)(i0 + r);
                s0p[r * (NN / 4) + v] = make_float4(fi, fi, fi, fi);
                s1p[r * (NN / 4) + v] = ramp;
            }
        }
    }

    // node_out for i0..i0+3 (read acc2 BEFORE reset)
    if (t < 4) {
        int i = i0 + t;
        float d2 = 1.f / g_deg[i];
        out[i * 2 + 0] = g_acc2[i * 2 + 0] + d2 * g_hw2[i * 2 + 0] + b2[0];
        out[i * 2 + 1] = g_acc2[i * 2 + 1] + d2 * g_hw2[i * 2 + 1] + b2[1];
    }
    __syncthreads();
    // reset state for next replay (4 rows per block)
    if (t < 64)              g_acc1[i0 * HH + t] = 0.f;
    else if (t < 72)         g_acc2[i0 * 2 + (t - 64)] = 0.f;
    else if (t < 76)         g_deg[i0 + (t - 72)] = 0.f;
    else if (t == 76 && b == 0) g_bar = 0u;
}

// ---------------- launch ----------------
extern "C" void kernel_launch(void* const* d_in, const int* in_sizes, int n_in,
                              void* d_out, int out_size) {
    const float* x   = (const float*)d_in[0];
    const void*  ei  = d_in[1];
    const float* W1  = (const float*)d_in[2];
    const float* b1  = (const float*)d_in[3];
    const float* W2  = (const float*)d_in[4];
    const float* b2  = (const float*)d_in[5];
    const float* Wc1 = (const float*)d_in[6];
    const float* bc1 = (const float*)d_in[7];
    const float* Wc2 = (const float*)d_in[8];
    const float* bc2 = (const float*)d_in[9];
    float* out = (float*)d_out;

    k_front<<<G1, TPB>>>(x, W1, ei, b1, W2, Wc1, bc1);
    k5_pair<<<NN / 4, TPB>>>(Wc2, bc2, b2, out);
}

// round 13
// speedup vs baseline: 2.5402x; 1.0462x over previous
#include <cuda_runtime.h>
#include <cuda_bf16.h>

#define NN   2048
#define EE   65536
#define FIN  128
#define HH   16
#define N2   (NN * NN)
#define G1   256
#define TPB  256

// ---------------- scratch (no allocations allowed) ----------------
__device__ __align__(16) float g_deg[NN];
__device__ __align__(16) float g_xw1[NN * HH];
__device__ __align__(16) float g_acc1[NN * HH];
__device__ __align__(16) float g_hw2[NN * 2];
__device__ __align__(16) float g_acc2[NN * 2];
__device__ __align__(16) float g_A[NN * HH];   // h @ Wc1[0:16] + bc1
__device__ __align__(16) float g_B[NN * HH];   // h @ Wc1[16:32]
__device__ unsigned g_bar;                     // grid barrier counter

// ---------------- per-thread edge_index layout detection ----------------
__device__ __forceinline__ bool detect_is32(const void* ei) {
    const unsigned long long* p = (const unsigned long long*)ei;
    unsigned long long v = p[0] | p[1] | p[2] | p[3] | p[4] | p[5] | p[6] | p[7];
    return v >= 2048ULL;
}

__device__ __forceinline__ void ld_edge(const void* ei, int e, bool is32,
                                        int& s, int& d) {
    if (is32) {
        s = ((const int*)ei)[e];
        d = ((const int*)ei)[EE + e];
    } else {
        s = (int)(((const long long*)ei)[e]);
        d = (int)(((const long long*)ei)[EE + e]);
    }
}

__device__ __forceinline__ void red_add_v4(float* p, float a, float b, float c, float d) {
    asm volatile("red.global.add.v4.f32 [%0], {%1,%2,%3,%4};"
                 :: "l"(p), "f"(a), "f"(b), "f"(c), "f"(d) : "memory");
}
__device__ __forceinline__ void red_add_v2(float* p, float a, float b) {
    asm volatile("red.global.add.v2.f32 [%0], {%1,%2};"
                 :: "l"(p), "f"(a), "f"(b) : "memory");
}

// sigmoid via single-MUFU tanh: sigmoid(s) = 0.5*tanh(0.5*s) + 0.5
__device__ __forceinline__ float sigmoid_tanh(float s) {
    float th;
    asm("tanh.approx.f32 %0, %1;" : "=f"(th) : "f"(0.5f * s));
    return fmaf(0.5f, th, 0.5f);
}

// Grid barrier: 256 blocks x 256 thr are guaranteed co-resident on 148 SMs.
__device__ __forceinline__ void gbar(unsigned target) {
    __syncthreads();
    if (threadIdx.x == 0) {
        asm volatile("red.release.gpu.global.add.u32 [%0], %1;"
                     :: "l"(&g_bar), "r"(1u) : "memory");
        unsigned v;
        do {
            asm volatile("ld.acquire.gpu.global.u32 %0, [%1];"
                         : "=r"(v) : "l"(&g_bar) : "memory");
            if (v < target) __nanosleep(32);
        } while (v < target);
    }
    __syncthreads();
}

// ================= k_front: GCN layers -> A,B,hw2,acc2 ====================
// Edge (s,d) and nrm are held in REGISTERS across the grid barriers, so
// phases B and D do no edge_index reloads and phase D does no loads at all.
__global__ void __launch_bounds__(TPB) k_front(
        const float* __restrict__ x,  const float* __restrict__ W1,
        const void*  __restrict__ ei, const float* __restrict__ b1,
        const float* __restrict__ W2, const float* __restrict__ Wc1,
        const float* __restrict__ bc1) {
    int id = blockIdx.x * TPB + threadIdx.x;     // 0..65535 == edge id
    bool is32 = detect_is32(ei);
    int se, de;
    ld_edge(ei, id, is32, se, de);               // edge loaded ONCE

    // ---- Phase A: degree + xw1 = x@W1 ----
    if (id < NN) atomicAdd(&g_deg[id], 1.f);     // self loop
    atomicAdd(&g_deg[de], 1.f);
    if (id < NN * HH) {
        int i = id >> 4, f = id & 15;
        const float4* xr = (const float4*)(x + i * FIN);
        float sum = 0.f;
        #pragma unroll
        for (int k4i = 0; k4i < FIN / 4; k4i++) {
            float4 xv = xr[k4i];
            int k = k4i * 4;
            sum = fmaf(xv.x, W1[(k + 0) * HH + f], sum);
            sum = fmaf(xv.y, W1[(k + 1) * HH + f], sum);
            sum = fmaf(xv.z, W1[(k + 2) * HH + f], sum);
            sum = fmaf(xv.w, W1[(k + 3) * HH + f], sum);
        }
        g_xw1[id] = sum;
    }
    gbar(G1);

    // ---- Phase B: scatter layer 1 (nrm computed once, kept for D) ----
    float nrm = rsqrtf(g_deg[se]) * rsqrtf(g_deg[de]);
    {
        const float4* xs = (const float4*)&g_xw1[se * HH];
        float4 v0 = xs[0], v1 = xs[1], v2 = xs[2], v3 = xs[3];
        float* ad = &g_acc1[de * HH];
        red_add_v4(ad + 0,  nrm * v0.x, nrm * v0.y, nrm * v0.z, nrm * v0.w);
        red_add_v4(ad + 4,  nrm * v1.x, nrm * v1.y, nrm * v1.z, nrm * v1.w);
        red_add_v4(ad + 8,  nrm * v2.x, nrm * v2.y, nrm * v2.z, nrm * v2.w);
        red_add_v4(ad + 12, nrm * v3.x, nrm * v3.y, nrm * v3.z, nrm * v3.w);
    }
    gbar(2 * G1);

    // ---- Phase C: h = relu(gcn1); hw2 = h@W2; A/B for pair MLP ----
    if (id < NN) {
        int i = id;
        float d2 = 1.f / g_deg[i];
        float h[HH];
        #pragma unroll
        for (int f = 0; f < HH; f++) {
            float v = g_acc1[i * HH + f] + d2 * g_xw1[i * HH + f] + b1[f];
            h[f] = fmaxf(v, 0.f);
        }
        float c0 = 0.f, c1 = 0.f;
        #pragma unroll
        for (int f = 0; f < HH; f++) {
            c0 = fmaf(h[f], W2[f * 2 + 0], c0);
            c1 = fmaf(h[f], W2[f * 2 + 1], c1);
        }
        g_hw2[i * 2 + 0] = c0;
        g_hw2[i * 2 + 1] = c1;
        #pragma unroll
        for (int o = 0; o < HH; o++) {
            float a = bc1[o], b = 0.f;
            #pragma unroll
            for (int f = 0; f < HH; f++) {
                a = fmaf(h[f], Wc1[f * HH + o], a);
                b = fmaf(h[f], Wc1[(HH + f) * HH + o], b);
            }
            g_A[i * HH + o] = a;
            g_B[i * HH + o] = b;
        }
    }
    gbar(3 * G1);

    // ---- Phase D: scatter layer 2 (reuses se/de/nrm from registers) ----
    red_add_v2(&g_acc2[de * 2], nrm * g_hw2[se * 2 + 0], nrm * g_hw2[se * 2 + 1]);
}

// ================= k5: pair MLP + index writes + node_out + reset =========
// grid = 1024: block b owns row group g=b>>1 (rows 4g..4g+3) and j-half
// (b&1). Warp lanes read CONSECUTIVE B rows -> coalesced; each B-row load
// feeds 4 output rows. Total B reads = 64MB, occupancy ~5 blocks/SM.
__global__ void __launch_bounds__(TPB) k5_pair(const float* __restrict__ Wc2,
                                               const float* __restrict__ bc2p,
                                               const float* __restrict__ b2,
                                               float* __restrict__ out) {
    int b = blockIdx.x;            // 0..1023
    int g = b >> 1;
    int half = b & 1;
    int i0 = g * 4;
    int t = threadIdx.x;
    int jbase = half * 1024;

    float A[4][HH], w[HH];
    #pragma unroll
    for (int r = 0; r < 4; r++) {
        const float4* ap = (const float4*)&g_A[(i0 + r) * HH];
        float4 v;
        v = ap[0]; A[r][0]=v.x;  A[r][1]=v.y;  A[r][2]=v.z;  A[r][3]=v.w;
        v = ap[1]; A[r][4]=v.x;  A[r][5]=v.y;  A[r][6]=v.z;  A[r][7]=v.w;
        v = ap[2]; A[r][8]=v.x;  A[r][9]=v.y;  A[r][10]=v.z; A[r][11]=v.w;
        v = ap[3]; A[r][12]=v.x; A[r][13]=v.y; A[r][14]=v.z; A[r][15]=v.w;
    }
    #pragma unroll
    for (int f = 0; f < HH; f++) w[f] = __ldg(&Wc2[f]);
    float bb = __ldg(&bc2p[0]);

    float* eo = out + NN * 2 + (long long)i0 * NN;

    #pragma unroll
    for (int q = 0; q < 4; q++) {
        int j = jbase + q * 256 + t;               // warp-consecutive rows
        const float4* bp = (const float4*)&g_B[j * HH];
        float4 q0 = bp[0], q1 = bp[1], q2 = bp[2], q3 = bp[3];
        float s0 = bb, s1 = bb, s2 = bb, s3 = bb;
#define PT(idx, comp) { float bv = comp; \
        s0 = fmaf(fmaxf(A[0][idx] + bv, 0.f), w[idx], s0); \
        s1 = fmaf(fmaxf(A[1][idx] + bv, 0.f), w[idx], s1); \
        s2 = fmaf(fmaxf(A[2][idx] + bv, 0.f), w[idx], s2); \
        s3 = fmaf(fmaxf(A[3][idx] + bv, 0.f), w[idx], s3); }
        PT(0,  q0.x) PT(1,  q0.y) PT(2,  q0.z) PT(3,  q0.w)
        PT(4,  q1.x) PT(5,  q1.y) PT(6,  q1.z) PT(7,  q1.w)
        PT(8,  q2.x) PT(9,  q2.y) PT(10, q2.z) PT(11, q2.w)
        PT(12, q3.x) PT(13, q3.y) PT(14, q3.z) PT(15, q3.w)
#undef PT
        eo[j]          = sigmoid_tanh(s0);         // coalesced STG.32
        eo[NN + j]     = sigmoid_tanh(s1);
        eo[2 * NN + j] = sigmoid_tanh(s2);
        eo[3 * NN + j] = sigmoid_tanh(s3);
    }

    // full_edge_index: this block writes its j-half of rows i0..i0+3
    {
        float4* s0p = (float4*)(out + NN * 2 + (long long)N2 + (long long)i0 * NN);
        float4* s1p = (float4*)(out + NN * 2 + 2LL * N2 + (long long)i0 * NN);
        int v = half * 256 + t;                    // float4 index within row
        float fj = (float)(v * 4);
        float4 ramp = make_float4(fj, fj + 1.f, fj + 2.f, fj + 3.f);
        #pragma unroll
        for (int r = 0; r < 4; r++) {
            float fi = (float)(i0 + r);
            s0p[r * (NN / 4) + v] = make_float4(fi, fi, fi, fi);
            s1p[r * (NN / 4) + v] = ramp;
        }
    }

    // node_out + reset: only the half==0 block of each group
    if (half == 0) {
        if (t < 4) {
            int i = i0 + t;
            float d2 = 1.f / g_deg[i];
            out[i * 2 + 0] = g_acc2[i * 2 + 0] + d2 * g_hw2[i * 2 + 0] + b2[0];
            out[i * 2 + 1] = g_acc2[i * 2 + 1] + d2 * g_hw2[i * 2 + 1] + b2[1];
        }
        __syncthreads();
        if (t < 64)              g_acc1[i0 * HH + t] = 0.f;
        else if (t < 72)         g_acc2[i0 * 2 + (t - 64)] = 0.f;
        else if (t < 76)         g_deg[i0 + (t - 72)] = 0.f;
        else if (t == 76 && b == 0) g_bar = 0u;
    }
}

// ---------------- launch ----------------
extern "C" void kernel_launch(void* const* d_in, const int* in_sizes, int n_in,
                              void* d_out, int out_size) {
    const float* x   = (const float*)d_in[0];
    const void*  ei  = d_in[1];
    const float* W1  = (const float*)d_in[2];
    const float* b1  = (const float*)d_in[3];
    const float* W2  = (const float*)d_in[4];
    const float* b2  = (const float*)d_in[5];
    const float* Wc1 = (const float*)d_in[6];
    const float* bc1 = (const float*)d_in[7];
    const float* Wc2 = (const float*)d_in[8];
    const float* bc2 = (const float*)d_in[9];
    float* out = (float*)d_out;

    k_front<<<G1, TPB>>>(x, W1, ei, b1, W2, Wc1, bc1);
    k5_pair<<<NN / 2, TPB>>>(Wc2, bc2, b2, out);
}

// round 17
// speedup vs baseline: 2.8303x; 1.1142x over previous
#include <cuda_runtime.h>
#include <cuda_bf16.h>

#define NN   2048
#define EE   65536
#define FIN  128
#define HH   16
#define N2   (NN * NN)
#define GF   128   // k_front blocks
#define TF   512   // k_front threads/block (128*512 = 65536)
#define TPB  256   // k5 threads/block

// ---------------- scratch (no allocations allowed) ----------------
__device__ __align__(16) float g_deg[NN];
__device__ __align__(16) float g_xw1[NN * HH];
__device__ __align__(16) float g_acc1[NN * HH];
__device__ __align__(16) float g_hw2[NN * 2];
__device__ __align__(16) float g_acc2[NN * 2];
__device__ __align__(16) float g_A[NN * HH];   // h @ Wc1[0:16] + bc1
__device__ __align__(16) float g_B[NN * HH];   // h @ Wc1[16:32]
__device__ unsigned g_bar;                     // grid barrier counter

// ---------------- per-thread edge_index layout detection ----------------
__device__ __forceinline__ bool detect_is32(const void* ei) {
    const unsigned long long* p = (const unsigned long long*)ei;
    unsigned long long v = p[0] | p[1] | p[2] | p[3] | p[4] | p[5] | p[6] | p[7];
    return v >= 2048ULL;
}

__device__ __forceinline__ void ld_edge(const void* ei, int e, bool is32,
                                        int& s, int& d) {
    if (is32) {
        s = ((const int*)ei)[e];
        d = ((const int*)ei)[EE + e];
    } else {
        s = (int)(((const long long*)ei)[e]);
        d = (int)(((const long long*)ei)[EE + e]);
    }
}

__device__ __forceinline__ void red_add_v4(float* p, float a, float b, float c, float d) {
    asm volatile("red.global.add.v4.f32 [%0], {%1,%2,%3,%4};"
                 :: "l"(p), "f"(a), "f"(b), "f"(c), "f"(d) : "memory");
}
__device__ __forceinline__ void red_add_v2(float* p, float a, float b) {
    asm volatile("red.global.add.v2.f32 [%0], {%1,%2};"
                 :: "l"(p), "f"(a), "f"(b) : "memory");
}

// sigmoid via single-MUFU tanh: sigmoid(s) = 0.5*tanh(0.5*s) + 0.5
__device__ __forceinline__ float sigmoid_tanh(float s) {
    float th;
    asm("tanh.approx.f32 %0, %1;" : "=f"(th) : "f"(0.5f * s));
    return fmaf(0.5f, th, 0.5f);
}

// Grid barrier: 128 blocks x 512 thr -> exactly one block per SM on 148 SMs,
// guaranteed co-resident. Tight acquire-poll (no nanosleep overshoot).
__device__ __forceinline__ void gbar(unsigned target) {
    __syncthreads();
    if (threadIdx.x == 0) {
        asm volatile("red.release.gpu.global.add.u32 [%0], %1;"
                     :: "l"(&g_bar), "r"(1u) : "memory");
        unsigned v;
        do {
            asm volatile("ld.acquire.gpu.global.u32 %0, [%1];"
                         : "=r"(v) : "l"(&g_bar) : "memory");
        } while (v < target);
    }
    __syncthreads();
}

// ================= k_front: GCN layers -> A,B,hw2,acc2 ====================
// 128 blocks x 512 threads: one block per SM (no intra-SM phase serialization).
// Edge (s,d) and nrm are carried in REGISTERS across the grid barriers.
__global__ void __launch_bounds__(TF) k_front(
        const float* __restrict__ x,  const float* __restrict__ W1,
        const void*  __restrict__ ei, const float* __restrict__ b1,
        const float* __restrict__ W2, const float* __restrict__ Wc1,
        const float* __restrict__ bc1) {
    int id = blockIdx.x * TF + threadIdx.x;      // 0..65535 == edge id
    bool is32 = detect_is32(ei);
    int se, de;
    ld_edge(ei, id, is32, se, de);               // edge loaded ONCE

    // ---- Phase A: degree + xw1 = x@W1 ----
    if (id < NN) atomicAdd(&g_deg[id], 1.f);     // self loop
    atomicAdd(&g_deg[de], 1.f);
    if (id < NN * HH) {
        int i = id >> 4, f = id & 15;
        const float4* xr = (const float4*)(x + i * FIN);
        float sum = 0.f;
        #pragma unroll
        for (int k4i = 0; k4i < FIN / 4; k4i++) {
            float4 xv = xr[k4i];
            int k = k4i * 4;
            sum = fmaf(xv.x, W1[(k + 0) * HH + f], sum);
            sum = fmaf(xv.y, W1[(k + 1) * HH + f], sum);
            sum = fmaf(xv.z, W1[(k + 2) * HH + f], sum);
            sum = fmaf(xv.w, W1[(k + 3) * HH + f], sum);
        }
        g_xw1[id] = sum;
    }
    gbar(GF);

    // ---- Phase B: scatter layer 1 (nrm computed once, kept for D) ----
    float nrm = rsqrtf(g_deg[se]) * rsqrtf(g_deg[de]);
    {
        const float4* xs = (const float4*)&g_xw1[se * HH];
        float4 v0 = xs[0], v1 = xs[1], v2 = xs[2], v3 = xs[3];
        float* ad = &g_acc1[de * HH];
        red_add_v4(ad + 0,  nrm * v0.x, nrm * v0.y, nrm * v0.z, nrm * v0.w);
        red_add_v4(ad + 4,  nrm * v1.x, nrm * v1.y, nrm * v1.z, nrm * v1.w);
        red_add_v4(ad + 8,  nrm * v2.x, nrm * v2.y, nrm * v2.z, nrm * v2.w);
        red_add_v4(ad + 12, nrm * v3.x, nrm * v3.y, nrm * v3.z, nrm * v3.w);
    }
    gbar(2 * GF);

    // ---- Phase C: h = relu(gcn1); hw2 = h@W2; A/B for pair MLP ----
    if (id < NN) {
        int i = id;
        float d2 = 1.f / g_deg[i];
        float h[HH];
        #pragma unroll
        for (int f = 0; f < HH; f++) {
            float v = g_acc1[i * HH + f] + d2 * g_xw1[i * HH + f] + b1[f];
            h[f] = fmaxf(v, 0.f);
        }
        float c0 = 0.f, c1 = 0.f;
        #pragma unroll
        for (int f = 0; f < HH; f++) {
            c0 = fmaf(h[f], W2[f * 2 + 0], c0);
            c1 = fmaf(h[f], W2[f * 2 + 1], c1);
        }
        g_hw2[i * 2 + 0] = c0;
        g_hw2[i * 2 + 1] = c1;
        #pragma unroll
        for (int o = 0; o < HH; o++) {
            float a = bc1[o], b = 0.f;
            #pragma unroll
            for (int f = 0; f < HH; f++) {
                a = fmaf(h[f], Wc1[f * HH + o], a);
                b = fmaf(h[f], Wc1[(HH + f) * HH + o], b);
            }
            g_A[i * HH + o] = a;
            g_B[i * HH + o] = b;
        }
    }
    gbar(3 * GF);

    // ---- Phase D: scatter layer 2 (reuses se/de/nrm from registers) ----
    red_add_v2(&g_acc2[de * 2], nrm * g_hw2[se * 2 + 0], nrm * g_hw2[se * 2 + 1]);
}

// ================= k5: pair MLP + index writes + node_out + reset =========
// EXACT R10 structure (measured 19.3us, 48 regs, occ 40.2%): block b owns
// rows i0..i0+3; thread t handles j = q*256 + t (warp-consecutive B rows).
__global__ void __launch_bounds__(TPB) k5_pair(const float* __restrict__ Wc2,
                                               const float* __restrict__ bc2p,
                                               const float* __restrict__ b2,
                                               float* __restrict__ out) {
    int b = blockIdx.x;            // 0..511
    int i0 = b * 4;
    int t = threadIdx.x;

    float A[4][HH], w[HH];
    #pragma unroll
    for (int r = 0; r < 4; r++) {
        const float4* ap = (const float4*)&g_A[(i0 + r) * HH];
        float4 v;
        v = ap[0]; A[r][0]=v.x;  A[r][1]=v.y;  A[r][2]=v.z;  A[r][3]=v.w;
        v = ap[1]; A[r][4]=v.x;  A[r][5]=v.y;  A[r][6]=v.z;  A[r][7]=v.w;
        v = ap[2]; A[r][8]=v.x;  A[r][9]=v.y;  A[r][10]=v.z; A[r][11]=v.w;
        v = ap[3]; A[r][12]=v.x; A[r][13]=v.y; A[r][14]=v.z; A[r][15]=v.w;
    }
    #pragma unroll
    for (int f = 0; f < HH; f++) w[f] = __ldg(&Wc2[f]);
    float bb = __ldg(&bc2p[0]);

    float* eo = out + NN * 2 + (long long)i0 * NN;

    #pragma unroll
    for (int q = 0; q < 8; q++) {
        int j = q * 256 + t;                       // warp-consecutive rows
        const float4* bp = (const float4*)&g_B[j * HH];
        float4 q0 = bp[0], q1 = bp[1], q2 = bp[2], q3 = bp[3];
        float s0 = bb, s1 = bb, s2 = bb, s3 = bb;
#define PT(idx, comp) { float bv = comp; \
        s0 = fmaf(fmaxf(A[0][idx] + bv, 0.f), w[idx], s0); \
        s1 = fmaf(fmaxf(A[1][idx] + bv, 0.f), w[idx], s1); \
        s2 = fmaf(fmaxf(A[2][idx] + bv, 0.f), w[idx], s2); \
        s3 = fmaf(fmaxf(A[3][idx] + bv, 0.f), w[idx], s3); }
        PT(0,  q0.x) PT(1,  q0.y) PT(2,  q0.z) PT(3,  q0.w)
        PT(4,  q1.x) PT(5,  q1.y) PT(6,  q1.z) PT(7,  q1.w)
        PT(8,  q2.x) PT(9,  q2.y) PT(10, q2.z) PT(11, q2.w)
        PT(12, q3.x) PT(13, q3.y) PT(14, q3.z) PT(15, q3.w)
#undef PT
        eo[j]          = sigmoid_tanh(s0);         // coalesced STG.32
        eo[NN + j]     = sigmoid_tanh(s1);
        eo[2 * NN + j] = sigmoid_tanh(s2);
        eo[3 * NN + j] = sigmoid_tanh(s3);
    }

    // full_edge_index rows for i0..i0+3 (independent of compute)
    {
        float4* s0p = (float4*)(out + NN * 2 + (long long)N2 + (long long)i0 * NN);
        float4* s1p = (float4*)(out + NN * 2 + 2LL * N2 + (long long)i0 * NN);
        #pragma unroll
        for (int it = 0; it < 2; it++) {
            int v = it * TPB + t;                  // 0..511 float4 per row
            float fj = (float)(v * 4);
            float4 ramp = make_float4(fj, fj + 1.f, fj + 2.f, fj + 3.f);
            #pragma unroll
            for (int r = 0; r < 4; r++) {
                float fi = (float)(i0 + r);
                s0p[r * (NN / 4) + v] = make_float4(fi, fi, fi, fi);
                s1p[r * (NN / 4) + v] = ramp;
            }
        }
    }

    // node_out for i0..i0+3 (read acc2 BEFORE reset)
    if (t < 4) {
        int i = i0 + t;
        float d2 = 1.f / g_deg[i];
        out[i * 2 + 0] = g_acc2[i * 2 + 0] + d2 * g_hw2[i * 2 + 0] + b2[0];
        out[i * 2 + 1] = g_acc2[i * 2 + 1] + d2 * g_hw2[i * 2 + 1] + b2[1];
    }
    __syncthreads();
    // reset state for next replay (4 rows per block)
    if (t < 64)              g_acc1[i0 * HH + t] = 0.f;
    else if (t < 72)         g_acc2[i0 * 2 + (t - 64)] = 0.f;
    else if (t < 76)         g_deg[i0 + (t - 72)] = 0.f;
    else if (t == 76 && b == 0) g_bar = 0u;
}

// ---------------- launch ----------------
extern "C" void kernel_launch(void* const* d_in, const int* in_sizes, int n_in,
                              void* d_out, int out_size) {
    const float* x   = (const float*)d_in[0];
    const void*  ei  = d_in[1];
    const float* W1  = (const float*)d_in[2];
    const float* b1  = (const float*)d_in[3];
    const float* W2  = (const float*)d_in[4];
    const float* b2  = (const float*)d_in[5];
    const float* Wc1 = (const float*)d_in[6];
    const float* bc1 = (const float*)d_in[7];
    const float* Wc2 = (const float*)d_in[8];
    const float* bc2 = (const float*)d_in[9];
    float* out = (float*)d_out;

    k_front<<<GF, TF>>>(x, W1, ei, b1, W2, Wc1, bc1);
    k5_pair<<<NN / 4, TPB>>>(Wc2, bc2, b2, out);
}